// round 14
// baseline (speedup 1.0000x reference)
#include <cuda_runtime.h>
#include <cuda_fp16.h>
#include <math.h>
#include <cstdint>

#define T_TOK   16384
#define DIM     2048
#define N_EXP   64
#define NC      128
#define TOPK    8

#define CTA_M   64
#define CTA_N   128
#define KT      32
#define NTILE   (DIM / KT)      // 64
#define PITCH   40              // halves per row: 80B, LDSM-conflict-free
#define ABUF    (CTA_M * PITCH) // 2560 halves per A array stage
#define BBUF    (CTA_N * PITCH) // 5120 halves per B array stage
#define SM_HALVES (4 * ABUF + 4 * BBUF)                 // 30720
#define DYN_SMEM  (SM_HALVES * 2 + 32 * 256 * 4)        // 94208 B

#define CLO     0.0009765625f   // 2^-10 cross-term scale

__device__ __half g_W0[(size_t)NC * DIM];
__device__ __half g_W1[(size_t)NC * DIM];

__device__ __forceinline__ void mma16(float c[4], const uint32_t a[4], const uint32_t b[2]) {
    asm volatile(
        "mma.sync.aligned.m16n8k16.row.col.f32.f16.f16.f32 "
        "{%0,%1,%2,%3}, {%4,%5,%6,%7}, {%8,%9}, {%0,%1,%2,%3};"
        : "+f"(c[0]), "+f"(c[1]), "+f"(c[2]), "+f"(c[3])
        : "r"(a[0]), "r"(a[1]), "r"(a[2]), "r"(a[3]), "r"(b[0]), "r"(b[1]));
}
__device__ __forceinline__ uint32_t smem_u32(const void* p) {
    uint32_t a;
    asm("{ .reg .u64 t; cvta.to.shared.u64 t, %1; cvt.u32.u64 %0, t; }"
        : "=r"(a) : "l"(p));
    return a;
}
__device__ __forceinline__ void ldsm4(uint32_t r[4], uint32_t addr) {
    asm volatile("ldmatrix.sync.aligned.m8n8.x4.shared.b16 {%0,%1,%2,%3}, [%4];"
                 : "=r"(r[0]), "=r"(r[1]), "=r"(r[2]), "=r"(r[3]) : "r"(addr));
}
__device__ __forceinline__ float softplus_f(float x) {
    return fmaxf(x, 0.0f) + log1pf(expf(-fabsf(x)));
}

// ---------------------------------------------------------------------------
// Kernel 0: split W into fp16 hi + scaled-lo (x1024)
// ---------------------------------------------------------------------------
__global__ void wsplit_kernel(const float* __restrict__ Wg,
                              const float* __restrict__ Wn) {
    const int i0 = (blockIdx.x * 256 + threadIdx.x) * 4;
#pragma unroll
    for (int f = 0; f < 2; f++) {
        const int i = i0 + f * 2;
        float2 w = (i < N_EXP * DIM)
                 ? *(const float2*)(Wg + i)
                 : *(const float2*)(Wn + (i - N_EXP * DIM));
        __half2 h0 = __floats2half2_rn(w.x, w.y);
        float2  b0 = __half22float2(h0);
        __half2 h1 = __floats2half2_rn((w.x - b0.x) * 1024.f,
                                       (w.y - b0.y) * 1024.f);
        *(__half2*)(g_W0 + i) = h0;
        *(__half2*)(g_W1 + i) = h1;
    }
}

// ---------------------------------------------------------------------------
// Kernel 1: fused router. Per CTA: 64 tokens x all 128 cols (H read ONCE),
// fp16 m16n8k16 3-term split GEMM (numerics bitwise = R13), then in-kernel
// softmax(64)+top-8 epilogue (logits staged in smem over dead A/B buffers).
// ---------------------------------------------------------------------------
__global__ void __launch_bounds__(256, 2)
router_fused(const float* __restrict__ H,
             const float* __restrict__ noise,
             float* __restrict__ out) {
    extern __shared__ __half smh[];
    __half* As0 = smh;                  // [2][CTA_M][PITCH]
    __half* As1 = As0 + 2 * ABUF;
    __half* Bs0 = As1 + 2 * ABUF;       // [2][CTA_N][PITCH]
    __half* Bs1 = Bs0 + 2 * BBUF;
    float*  acc2s = (float*)(Bs1 + 2 * BBUF);   // [32][256]
    float*  ltile = (float*)smh;        // [64][128] — aliases A/B post-mainloop

    const int tid  = threadIdx.x;
    const int lane = tid & 31;
    const int wid  = tid >> 5;
    const int wm   = wid & 3;           // 16-row group
    const int wn   = wid >> 2;          // 64-col group (0..1)
    const int m0   = blockIdx.x * CTA_M;
    const int fr   = lane >> 2;
    const int fc   = lane & 3;

    // ldmatrix per-lane geometry
    const int a_lm_row = (lane & 7) + ((lane >> 3) & 1) * 8;
    const int a_lm_k   = (lane >> 4) * 8;
    const int b_lm_row = (lane & 7) + (lane >> 4) * 8;
    const int b_lm_k   = ((lane >> 3) & 1) * 8;

    const uint32_t uA0 = smem_u32(As0), uA1 = smem_u32(As1);
    const uint32_t uB0 = smem_u32(Bs0), uB1 = smem_u32(Bs1);
    const uint32_t aoff = (uint32_t)(((wm * 16 + a_lm_row) * PITCH + a_lm_k) * 2);
    const uint32_t boff = (uint32_t)(((wn * 64 + b_lm_row) * PITCH + b_lm_k) * 2);

    // loaders: A 8 floats/thread; B 16 halves/array/thread
    const int a_row = tid >> 2, a_kh = (tid & 3) * 8;
    const int b_row = tid >> 1, b_kh = (tid & 1) * 16;
    const float* aG  = H + (size_t)(m0 + a_row) * DIM;
    const __half* b0G = g_W0 + (size_t)b_row * DIM;
    const __half* b1G = g_W1 + (size_t)b_row * DIM;

    float acc_a[8][4], acc_c[8][4];
#pragma unroll
    for (int j = 0; j < 8; j++)
#pragma unroll
        for (int r = 0; r < 4; r++) { acc_a[j][r] = 0.f; acc_c[j][r] = 0.f; }
#pragma unroll
    for (int r = 0; r < 32; r++) acc2s[r * 256 + tid] = 0.f;

    float4 av[2];
    uint4  bv0[2], bv1[2];
#pragma unroll
    for (int f = 0; f < 2; f++) {
        av[f]  = *(const float4*)(aG + a_kh + f * 4);
        bv0[f] = *(const uint4*)(b0G + b_kh + f * 8);
        bv1[f] = *(const uint4*)(b1G + b_kh + f * 8);
    }

    auto store_a = [&](int stage) {
        __half* d0 = As0 + stage * ABUF + a_row * PITCH + a_kh;
        __half* d1 = As1 + stage * ABUF + a_row * PITCH + a_kh;
#pragma unroll
        for (int f = 0; f < 2; f++) {
            float fx = av[f].x, fy = av[f].y, fz = av[f].z, fw = av[f].w;
            __half2 p0 = __floats2half2_rn(fx, fy);
            __half2 p1 = __floats2half2_rn(fz, fw);
            float2 c0 = __half22float2(p0), c1 = __half22float2(p1);
            __half2 q0 = __floats2half2_rn((fx - c0.x) * 1024.f, (fy - c0.y) * 1024.f);
            __half2 q1 = __floats2half2_rn((fz - c1.x) * 1024.f, (fw - c1.y) * 1024.f);
            *(__half2*)(d0 + f * 4)     = p0;
            *(__half2*)(d0 + f * 4 + 2) = p1;
            *(__half2*)(d1 + f * 4)     = q0;
            *(__half2*)(d1 + f * 4 + 2) = q1;
        }
    };
    auto store_b = [&](int stage) {
        __half* d0 = Bs0 + stage * BBUF + b_row * PITCH + b_kh;
        __half* d1 = Bs1 + stage * BBUF + b_row * PITCH + b_kh;
#pragma unroll
        for (int f = 0; f < 2; f++) {
            *(uint4*)(d0 + f * 8) = bv0[f];
            *(uint4*)(d1 + f * 8) = bv1[f];
        }
    };

    store_a(0); store_b(0);
    __syncthreads();

    for (int t = 0; t < NTILE; t++) {
        const int s = t & 1;
        const bool more = (t + 1 < NTILE);
        if (more) {
            const int kb = (t + 1) * KT;
#pragma unroll
            for (int f = 0; f < 2; f++) {
                av[f]  = *(const float4*)(aG + kb + a_kh + f * 4);
                bv0[f] = *(const uint4*)(b0G + kb + b_kh + f * 8);
                bv1[f] = *(const uint4*)(b1G + kb + b_kh + f * 8);
            }
        }

        const uint32_t stA0 = uA0 + (uint32_t)(s * ABUF * 2) + aoff;
        const uint32_t stA1 = uA1 + (uint32_t)(s * ABUF * 2) + aoff;
        const uint32_t stB0 = uB0 + (uint32_t)(s * BBUF * 2) + boff;
        const uint32_t stB1 = uB1 + (uint32_t)(s * BBUF * 2) + boff;

#pragma unroll
        for (int ks = 0; ks < 2; ks++) {
            const uint32_t kb2 = (uint32_t)(ks * 16 * 2);
            uint32_t a0f[4], a1f[4], b0f[8][2], b1f[8][2];
            ldsm4(a0f, stA0 + kb2);
#pragma unroll
            for (int p = 0; p < 4; p++) {
                uint32_t q[4];
                ldsm4(q, stB0 + kb2 + (uint32_t)(p * 16 * PITCH * 2));
                b0f[2*p][0] = q[0]; b0f[2*p][1] = q[1];
                b0f[2*p+1][0] = q[2]; b0f[2*p+1][1] = q[3];
            }
#pragma unroll
            for (int nt = 0; nt < 8; nt++) mma16(acc_a[nt], a0f, b0f[nt]);
#pragma unroll
            for (int p = 0; p < 4; p++) {
                uint32_t q[4];
                ldsm4(q, stB1 + kb2 + (uint32_t)(p * 16 * PITCH * 2));
                b1f[2*p][0] = q[0]; b1f[2*p][1] = q[1];
                b1f[2*p+1][0] = q[2]; b1f[2*p+1][1] = q[3];
            }
#pragma unroll
            for (int nt = 0; nt < 8; nt++) mma16(acc_c[nt], a0f, b1f[nt]);
            ldsm4(a1f, stA1 + kb2);
#pragma unroll
            for (int nt = 0; nt < 8; nt++) mma16(acc_c[nt], a1f, b0f[nt]);
        }

        if (more) { store_a(s ^ 1); store_b(s ^ 1); }
        __syncthreads();

        if ((t & 1) == 1) {   // 64-k RN cascade (same expression as R13)
#pragma unroll
            for (int nt = 0; nt < 8; nt++)
#pragma unroll
                for (int r = 0; r < 4; r++) {
                    const int idx = nt * 4 + r;
                    acc2s[idx * 256 + tid] += acc_a[nt][r] + acc_c[nt][r] * CLO;
                    acc_a[nt][r] = 0.f;
                    acc_c[nt][r] = 0.f;
                }
        }
    }

    // stage logits tile in smem (aliases dead A/B buffers)
#pragma unroll
    for (int nt = 0; nt < 8; nt++) {
        const int row = wm * 16 + fr;
        const int col = wn * 64 + nt * 8 + fc * 2;
        const int idx = nt * 4;
        float v0 = acc2s[(idx + 0) * 256 + tid];
        float v1 = acc2s[(idx + 1) * 256 + tid];
        float v2 = acc2s[(idx + 2) * 256 + tid];
        float v3 = acc2s[(idx + 3) * 256 + tid];
        *(float2*)&ltile[row * NC + col]       = make_float2(v0, v1);
        *(float2*)&ltile[(row + 8) * NC + col] = make_float2(v2, v3);
    }
    __syncthreads();

    // fused softmax(64) + top-8: 8 tokens per warp
    for (int tk = 0; tk < 8; tk++) {
        const int tok  = wid * 8 + tk;
        const int gtok = m0 + tok;
        const float* row = ltile + tok * NC;
        const float* nz  = noise + (size_t)gtok * N_EXP;

        float g0 = row[lane]      + nz[lane]      * softplus_f(row[64 + lane]);
        float g1 = row[lane + 32] + nz[lane + 32] * softplus_f(row[96 + lane]);

        float mx = fmaxf(g0, g1);
#pragma unroll
        for (int o = 16; o > 0; o >>= 1) mx = fmaxf(mx, __shfl_xor_sync(0xffffffffu, mx, o));
        float e0 = expf(g0 - mx), e1 = expf(g1 - mx);
        float s = e0 + e1;
#pragma unroll
        for (int o = 16; o > 0; o >>= 1) s += __shfl_xor_sync(0xffffffffu, s, o);
        const float inv = 1.0f / s;
        float p0 = e0 * inv, p1 = e1 * inv;

        float* gates = out + (size_t)2 * T_TOK * TOPK + (size_t)gtok * N_EXP;
        gates[lane]      = p0;
        gates[lane + 32] = p1;

        float v0 = p0, v1 = p1;
        float* vals = out + (size_t)gtok * TOPK;
        float* inds = out + (size_t)T_TOK * TOPK + (size_t)gtok * TOPK;

#pragma unroll
        for (int r = 0; r < TOPK; r++) {
            float cv; int ci;
            if (v0 >= v1) { cv = v0; ci = lane; }
            else          { cv = v1; ci = lane + 32; }
#pragma unroll
            for (int o = 16; o > 0; o >>= 1) {
                float ov = __shfl_xor_sync(0xffffffffu, cv, o);
                int   oi = __shfl_xor_sync(0xffffffffu, ci, o);
                if (ov > cv || (ov == cv && oi < ci)) { cv = ov; ci = oi; }
            }
            if (lane == 0) { vals[r] = cv; inds[r] = (float)ci; }
            if (ci == lane)      v0 = -INFINITY;
            if (ci == lane + 32) v1 = -INFINITY;
        }
    }
}

// ---------------------------------------------------------------------------
extern "C" void kernel_launch(void* const* d_in, const int* in_sizes, int n_in,
                              void* d_out, int out_size) {
    const float* H     = (const float*)d_in[0];
    const float* Wg    = (const float*)d_in[1];
    const float* Wn    = (const float*)d_in[2];
    const float* noise = (const float*)d_in[3];
    float* out = (float*)d_out;

    cudaFuncSetAttribute(router_fused,
                         cudaFuncAttributeMaxDynamicSharedMemorySize, DYN_SMEM);

    wsplit_kernel<<<256, 256>>>(Wg, Wn);
    router_fused<<<T_TOK / CTA_M, 256, DYN_SMEM>>>(H, noise, out);
}

// round 15
// speedup vs baseline: 1.6872x; 1.6872x over previous
#include <cuda_runtime.h>
#include <cuda_fp16.h>
#include <math.h>
#include <cstdint>

#define T_TOK   16384
#define DIM     2048
#define N_EXP   64
#define NC      128
#define TOPK    8

#define CTA_M   128
#define CTA_N   64
#define KT      32
#define NTILE   (DIM / KT)      // 64
#define PITCH   40              // halves per row: 80B, LDSM-conflict-free
#define ABUF    (CTA_M * PITCH)
#define BBUF    (CTA_N * PITCH)
#define SM_HALVES (4 * ABUF + 4 * BBUF)
#define DYN_SMEM  (SM_HALVES * 2 + 32 * 256 * 4)    // 94208 B

#define CLO     0.0009765625f   // 2^-10 cross-term scale

__device__ float  g_logits[(size_t)T_TOK * NC];
__device__ __half g_W0[(size_t)NC * DIM];
__device__ __half g_W1[(size_t)NC * DIM];

__device__ __forceinline__ void mma16(float c[4], const uint32_t a[4], const uint32_t b[2]) {
    asm volatile(
        "mma.sync.aligned.m16n8k16.row.col.f32.f16.f16.f32 "
        "{%0,%1,%2,%3}, {%4,%5,%6,%7}, {%8,%9}, {%0,%1,%2,%3};"
        : "+f"(c[0]), "+f"(c[1]), "+f"(c[2]), "+f"(c[3])
        : "r"(a[0]), "r"(a[1]), "r"(a[2]), "r"(a[3]), "r"(b[0]), "r"(b[1]));
}
__device__ __forceinline__ uint32_t smem_u32(const void* p) {
    uint32_t a;
    asm("{ .reg .u64 t; cvta.to.shared.u64 t, %1; cvt.u32.u64 %0, t; }"
        : "=r"(a) : "l"(p));
    return a;
}
__device__ __forceinline__ void ldsm4(uint32_t r[4], uint32_t addr) {
    asm volatile("ldmatrix.sync.aligned.m8n8.x4.shared.b16 {%0,%1,%2,%3}, [%4];"
                 : "=r"(r[0]), "=r"(r[1]), "=r"(r[2]), "=r"(r[3]) : "r"(addr));
}
__device__ __forceinline__ void cp16(uint32_t dst, const void* src) {
    asm volatile("cp.async.ca.shared.global [%0], [%1], 16;"
                 :: "r"(dst), "l"(src) : "memory");
}
#define CP_COMMIT() asm volatile("cp.async.commit_group;" ::: "memory")
#define CP_WAIT0()  asm volatile("cp.async.wait_group 0;" ::: "memory")

// ---------------------------------------------------------------------------
// Kernel 0: split W into fp16 hi + scaled-lo (x1024)
// ---------------------------------------------------------------------------
__global__ void wsplit_kernel(const float* __restrict__ Wg,
                              const float* __restrict__ Wn) {
    const int i0 = (blockIdx.x * 256 + threadIdx.x) * 4;
#pragma unroll
    for (int f = 0; f < 2; f++) {
        const int i = i0 + f * 2;
        float2 w = (i < N_EXP * DIM)
                 ? *(const float2*)(Wg + i)
                 : *(const float2*)(Wn + (i - N_EXP * DIM));
        __half2 h0 = __floats2half2_rn(w.x, w.y);
        float2  b0 = __half22float2(h0);
        __half2 h1 = __floats2half2_rn((w.x - b0.x) * 1024.f,
                                       (w.y - b0.y) * 1024.f);
        *(__half2*)(g_W0 + i) = h0;
        *(__half2*)(g_W1 + i) = h1;
    }
}

// ---------------------------------------------------------------------------
// Kernel 1: fp16 m16n8k16 3-term split GEMM — structure identical to R13
// (proven 151.6). CHANGE: B staging via cp.async (no bv registers, no B
// LDG->STS) to relieve the mainloop register pressure at the 128-reg cap.
// Fragment values & MMA order unchanged -> outputs bitwise identical.
// ---------------------------------------------------------------------------
__global__ void __launch_bounds__(256, 2)
router_gemm_f16(const float* __restrict__ H) {
    extern __shared__ __half smh[];
    __half* As0 = smh;                  // [2][CTA_M][PITCH]
    __half* As1 = As0 + 2 * ABUF;
    __half* Bs0 = As1 + 2 * ABUF;       // [2][CTA_N][PITCH]
    __half* Bs1 = Bs0 + 2 * BBUF;
    float*  acc2s = (float*)(Bs1 + 2 * BBUF);   // [32][256]

    const int tid  = threadIdx.x;
    const int lane = tid & 31;
    const int wid  = tid >> 5;
    const int wm   = wid & 3;
    const int wn   = wid >> 2;
    const int m0   = blockIdx.x * CTA_M;
    const int fr   = lane >> 2;
    const int fc   = lane & 3;

    // ldmatrix per-lane geometry
    const int a_lm_row = (lane & 7) + ((lane >> 3) & 1) * 8;
    const int a_lm_k   = (lane >> 4) * 8;
    const int b_lm_row = (lane & 7) + (lane >> 4) * 8;
    const int b_lm_k   = ((lane >> 3) & 1) * 8;

    const uint32_t uA0 = smem_u32(As0), uA1 = smem_u32(As1);
    const uint32_t uB0 = smem_u32(Bs0), uB1 = smem_u32(Bs1);
    const uint32_t aoff = (uint32_t)(((wm * 32 + a_lm_row) * PITCH + a_lm_k) * 2);
    const uint32_t boff = (uint32_t)(((wn * 32 + b_lm_row) * PITCH + b_lm_k) * 2);

    // loaders
    const int a_row = tid >> 1, a_kh = (tid & 1) * 16;      // A: 16 floats/thread
    const int b_row = tid >> 2, b_k8 = (tid & 3) * 8;       // B: 1 cp16/array/thread
    const float* aG  = H + (size_t)(m0 + a_row) * DIM;
    const __half* b0G = g_W0 + (size_t)(blockIdx.y * CTA_N + b_row) * DIM;
    const __half* b1G = g_W1 + (size_t)(blockIdx.y * CTA_N + b_row) * DIM;
    const uint32_t b_sm_off = (uint32_t)((b_row * PITCH + b_k8) * 2);

    float acc_a[2][4][4], acc_c[2][4][4];
#pragma unroll
    for (int i = 0; i < 2; i++)
#pragma unroll
        for (int j = 0; j < 4; j++)
#pragma unroll
            for (int r = 0; r < 4; r++) { acc_a[i][j][r] = 0.f; acc_c[i][j][r] = 0.f; }
#pragma unroll
    for (int r = 0; r < 32; r++) acc2s[r * 256 + tid] = 0.f;

    float4 av[4];
#pragma unroll
    for (int f = 0; f < 4; f++) av[f] = *(const float4*)(aG + a_kh + f * 4);

    auto store_a = [&](int stage) {
        __half* d0 = As0 + stage * ABUF + a_row * PITCH + a_kh;
        __half* d1 = As1 + stage * ABUF + a_row * PITCH + a_kh;
#pragma unroll
        for (int f = 0; f < 4; f++) {
            float fx = av[f].x, fy = av[f].y, fz = av[f].z, fw = av[f].w;
            __half2 p0 = __floats2half2_rn(fx, fy);
            __half2 p1 = __floats2half2_rn(fz, fw);
            float2 c0 = __half22float2(p0), c1 = __half22float2(p1);
            __half2 q0 = __floats2half2_rn((fx - c0.x) * 1024.f, (fy - c0.y) * 1024.f);
            __half2 q1 = __floats2half2_rn((fz - c1.x) * 1024.f, (fw - c1.y) * 1024.f);
            *(__half2*)(d0 + f * 4)     = p0;
            *(__half2*)(d0 + f * 4 + 2) = p1;
            *(__half2*)(d1 + f * 4)     = q0;
            *(__half2*)(d1 + f * 4 + 2) = q1;
        }
    };
    // B stage via cp.async: one 16B copy per array per thread
    auto issue_b = [&](int t, int stage) {
        cp16(uB0 + (uint32_t)(stage * BBUF * 2) + b_sm_off, b0G + t * KT + b_k8);
        cp16(uB1 + (uint32_t)(stage * BBUF * 2) + b_sm_off, b1G + t * KT + b_k8);
        CP_COMMIT();
    };

    store_a(0);
    issue_b(0, 0);
    CP_WAIT0();
    __syncthreads();

    for (int t = 0; t < NTILE; t++) {
        const int s = t & 1;
        const bool more = (t + 1 < NTILE);
        if (more) {
            issue_b(t + 1, s ^ 1);      // async B for next tile
            const int kb = (t + 1) * KT;
#pragma unroll
            for (int f = 0; f < 4; f++) av[f] = *(const float4*)(aG + kb + a_kh + f * 4);
        }

        const uint32_t stA0 = uA0 + (uint32_t)(s * ABUF * 2) + aoff;
        const uint32_t stA1 = uA1 + (uint32_t)(s * ABUF * 2) + aoff;
        const uint32_t stB0 = uB0 + (uint32_t)(s * BBUF * 2) + boff;
        const uint32_t stB1 = uB1 + (uint32_t)(s * BBUF * 2) + boff;

#pragma unroll
        for (int ks = 0; ks < 2; ks++) {
            const uint32_t kb2 = (uint32_t)(ks * 16 * 2);
            uint32_t a0f[2][4], b0f[4][2], b1f[4][2], a1f[2][4];
#pragma unroll
            for (int mt = 0; mt < 2; mt++)
                ldsm4(a0f[mt], stA0 + kb2 + (uint32_t)(mt * 16 * PITCH * 2));
            {
                uint32_t q[4];
                ldsm4(q, stB0 + kb2);
                b0f[0][0] = q[0]; b0f[0][1] = q[1]; b0f[1][0] = q[2]; b0f[1][1] = q[3];
                ldsm4(q, stB0 + kb2 + (uint32_t)(16 * PITCH * 2));
                b0f[2][0] = q[0]; b0f[2][1] = q[1]; b0f[3][0] = q[2]; b0f[3][1] = q[3];
            }
#pragma unroll
            for (int mt = 0; mt < 2; mt++)
#pragma unroll
                for (int nt = 0; nt < 4; nt++) mma16(acc_a[mt][nt], a0f[mt], b0f[nt]);
            {
                uint32_t q[4];
                ldsm4(q, stB1 + kb2);
                b1f[0][0] = q[0]; b1f[0][1] = q[1]; b1f[1][0] = q[2]; b1f[1][1] = q[3];
                ldsm4(q, stB1 + kb2 + (uint32_t)(16 * PITCH * 2));
                b1f[2][0] = q[0]; b1f[2][1] = q[1]; b1f[3][0] = q[2]; b1f[3][1] = q[3];
            }
#pragma unroll
            for (int mt = 0; mt < 2; mt++)
#pragma unroll
                for (int nt = 0; nt < 4; nt++) mma16(acc_c[mt][nt], a0f[mt], b1f[nt]);
#pragma unroll
            for (int mt = 0; mt < 2; mt++)
                ldsm4(a1f[mt], stA1 + kb2 + (uint32_t)(mt * 16 * PITCH * 2));
#pragma unroll
            for (int mt = 0; mt < 2; mt++)
#pragma unroll
                for (int nt = 0; nt < 4; nt++) mma16(acc_c[mt][nt], a1f[mt], b0f[nt]);
        }

        if (more) store_a(s ^ 1);
        CP_WAIT0();
        __syncthreads();

        if ((t & 1) == 1) {   // 64-k RN cascade (same expression as R13)
#pragma unroll
            for (int mt = 0; mt < 2; mt++)
#pragma unroll
                for (int nt = 0; nt < 4; nt++)
#pragma unroll
                    for (int r = 0; r < 4; r++) {
                        const int idx = (mt * 4 + nt) * 4 + r;
                        acc2s[idx * 256 + tid] += acc_a[mt][nt][r] + acc_c[mt][nt][r] * CLO;
                        acc_a[mt][nt][r] = 0.f;
                        acc_c[mt][nt][r] = 0.f;
                    }
        }
    }

    // epilogue
#pragma unroll
    for (int mt = 0; mt < 2; mt++)
#pragma unroll
        for (int nt = 0; nt < 4; nt++) {
            const int row = m0 + wm * 32 + mt * 16 + fr;
            const int col = blockIdx.y * CTA_N + wn * 32 + nt * 8 + fc * 2;
            const int idx = (mt * 4 + nt) * 4;
            float v0 = acc2s[(idx + 0) * 256 + tid];
            float v1 = acc2s[(idx + 1) * 256 + tid];
            float v2 = acc2s[(idx + 2) * 256 + tid];
            float v3 = acc2s[(idx + 3) * 256 + tid];
            *(float2*)&g_logits[(size_t)row * NC + col]       = make_float2(v0, v1);
            *(float2*)&g_logits[(size_t)(row + 8) * NC + col] = make_float2(v2, v3);
        }
}

// ---------------------------------------------------------------------------
// Kernel 2: one warp per token — noisy logits, softmax(64), top-8 desc
// ---------------------------------------------------------------------------
__device__ __forceinline__ float softplus_f(float x) {
    return fmaxf(x, 0.0f) + log1pf(expf(-fabsf(x)));
}

__global__ void __launch_bounds__(256)
router_topk_kernel(const float* __restrict__ noise, float* __restrict__ out) {
    const int warp = (blockIdx.x * blockDim.x + threadIdx.x) >> 5;
    const int lane = threadIdx.x & 31;
    if (warp >= T_TOK) return;

    const float* row = g_logits + (size_t)warp * NC;
    const float* nz  = noise + (size_t)warp * N_EXP;

    float g0 = row[lane]      + nz[lane]      * softplus_f(row[64 + lane]);
    float g1 = row[lane + 32] + nz[lane + 32] * softplus_f(row[96 + lane]);

    float mx = fmaxf(g0, g1);
#pragma unroll
    for (int o = 16; o > 0; o >>= 1) mx = fmaxf(mx, __shfl_xor_sync(0xffffffffu, mx, o));
    float e0 = expf(g0 - mx), e1 = expf(g1 - mx);
    float s = e0 + e1;
#pragma unroll
    for (int o = 16; o > 0; o >>= 1) s += __shfl_xor_sync(0xffffffffu, s, o);
    const float inv = 1.0f / s;
    float p0 = e0 * inv, p1 = e1 * inv;

    float* gates = out + (size_t)2 * T_TOK * TOPK + (size_t)warp * N_EXP;
    gates[lane]      = p0;
    gates[lane + 32] = p1;

    float v0 = p0, v1 = p1;
    float* vals = out + (size_t)warp * TOPK;
    float* inds = out + (size_t)T_TOK * TOPK + (size_t)warp * TOPK;

#pragma unroll
    for (int r = 0; r < TOPK; r++) {
        float cv; int ci;
        if (v0 >= v1) { cv = v0; ci = lane; }
        else          { cv = v1; ci = lane + 32; }
#pragma unroll
        for (int o = 16; o > 0; o >>= 1) {
            float ov = __shfl_xor_sync(0xffffffffu, cv, o);
            int   oi = __shfl_xor_sync(0xffffffffu, ci, o);
            if (ov > cv || (ov == cv && oi < ci)) { cv = ov; ci = oi; }
        }
        if (lane == 0) { vals[r] = cv; inds[r] = (float)ci; }
        if (ci == lane)      v0 = -INFINITY;
        if (ci == lane + 32) v1 = -INFINITY;
    }
}

// ---------------------------------------------------------------------------
extern "C" void kernel_launch(void* const* d_in, const int* in_sizes, int n_in,
                              void* d_out, int out_size) {
    const float* H     = (const float*)d_in[0];
    const float* Wg    = (const float*)d_in[1];
    const float* Wn    = (const float*)d_in[2];
    const float* noise = (const float*)d_in[3];
    float* out = (float*)d_out;

    cudaFuncSetAttribute(router_gemm_f16,
                         cudaFuncAttributeMaxDynamicSharedMemorySize, DYN_SMEM);

    wsplit_kernel<<<256, 256>>>(Wg, Wn);
    dim3 grid(T_TOK / CTA_M, 2);
    router_gemm_f16<<<grid, 256, DYN_SMEM>>>(H);
    router_topk_kernel<<<(T_TOK * 32) / 256, 256>>>(noise, out);
}

// round 16
// speedup vs baseline: 1.8201x; 1.0788x over previous
#include <cuda_runtime.h>
#include <cuda_fp16.h>
#include <math.h>
#include <cstdint>

#define T_TOK   16384
#define DIM     2048
#define N_EXP   64
#define NC      128
#define TOPK    8

#define CTA_M   128
#define CTA_N   64
#define KT      32
#define NTILE   (DIM / KT)      // 64
#define PITCH   40              // halves per row: 80B, LDSM-conflict-free
#define ABUF    (CTA_M * PITCH)
#define BBUF    (CTA_N * PITCH)
#define SM_HALVES (4 * ABUF + 4 * BBUF)
#define DYN_SMEM  (SM_HALVES * 2 + 32 * 256 * 4)    // 94208 B

#define CLO     0.0009765625f   // 2^-10 cross-term scale

__device__ float  g_logits[(size_t)T_TOK * NC];
__device__ __half g_W0[(size_t)NC * DIM];
__device__ __half g_W1[(size_t)NC * DIM];

__device__ __forceinline__ void mma16(float c[4], const uint32_t a[4], const uint32_t b[2]) {
    asm volatile(
        "mma.sync.aligned.m16n8k16.row.col.f32.f16.f16.f32 "
        "{%0,%1,%2,%3}, {%4,%5,%6,%7}, {%8,%9}, {%0,%1,%2,%3};"
        : "+f"(c[0]), "+f"(c[1]), "+f"(c[2]), "+f"(c[3])
        : "r"(a[0]), "r"(a[1]), "r"(a[2]), "r"(a[3]), "r"(b[0]), "r"(b[1]));
}
__device__ __forceinline__ uint32_t smem_u32(const void* p) {
    uint32_t a;
    asm("{ .reg .u64 t; cvta.to.shared.u64 t, %1; cvt.u32.u64 %0, t; }"
        : "=r"(a) : "l"(p));
    return a;
}
__device__ __forceinline__ void ldsm4(uint32_t r[4], uint32_t addr) {
    asm volatile("ldmatrix.sync.aligned.m8n8.x4.shared.b16 {%0,%1,%2,%3}, [%4];"
                 : "=r"(r[0]), "=r"(r[1]), "=r"(r[2]), "=r"(r[3]) : "r"(addr));
}
__device__ __forceinline__ void cp16(uint32_t dst, const void* src) {
    asm volatile("cp.async.ca.shared.global [%0], [%1], 16;"
                 :: "r"(dst), "l"(src) : "memory");
}
#define CP_COMMIT() asm volatile("cp.async.commit_group;" ::: "memory")
#define CP_WAIT0()  asm volatile("cp.async.wait_group 0;" ::: "memory")

// ---------------------------------------------------------------------------
// Kernel 0: split W into fp16 hi + scaled-lo (x1024)
// ---------------------------------------------------------------------------
__global__ void wsplit_kernel(const float* __restrict__ Wg,
                              const float* __restrict__ Wn) {
    const int i0 = (blockIdx.x * 256 + threadIdx.x) * 4;
#pragma unroll
    for (int f = 0; f < 2; f++) {
        const int i = i0 + f * 2;
        float2 w = (i < N_EXP * DIM)
                 ? *(const float2*)(Wg + i)
                 : *(const float2*)(Wn + (i - N_EXP * DIM));
        __half2 h0 = __floats2half2_rn(w.x, w.y);
        float2  b0 = __half22float2(h0);
        __half2 h1 = __floats2half2_rn((w.x - b0.x) * 1024.f,
                                       (w.y - b0.y) * 1024.f);
        *(__half2*)(g_W0 + i) = h0;
        *(__half2*)(g_W1 + i) = h1;
    }
}

// ---------------------------------------------------------------------------
// Kernel 1: fp16 m16n8k16 3-term split GEMM (R15 skeleton).
// Changes: cascade every 4 tiles (128k chunks), acc2 in float2 pair layout
// (64-bit LDS/STS), store_a 64-bit packed STS. Fragment values & MMA order
// unchanged; per-element add order unchanged except chunk boundaries.
// ---------------------------------------------------------------------------
__global__ void __launch_bounds__(256, 2)
router_gemm_f16(const float* __restrict__ H) {
    extern __shared__ __half smh[];
    __half* As0 = smh;                  // [2][CTA_M][PITCH]
    __half* As1 = As0 + 2 * ABUF;
    __half* Bs0 = As1 + 2 * ABUF;       // [2][CTA_N][PITCH]
    __half* Bs1 = Bs0 + 2 * BBUF;
    float2* acc2s = (float2*)(Bs1 + 2 * BBUF);  // [16 pairs][256] float2

    const int tid  = threadIdx.x;
    const int lane = tid & 31;
    const int wid  = tid >> 5;
    const int wm   = wid & 3;
    const int wn   = wid >> 2;
    const int m0   = blockIdx.x * CTA_M;
    const int fr   = lane >> 2;
    const int fc   = lane & 3;

    // ldmatrix per-lane geometry
    const int a_lm_row = (lane & 7) + ((lane >> 3) & 1) * 8;
    const int a_lm_k   = (lane >> 4) * 8;
    const int b_lm_row = (lane & 7) + (lane >> 4) * 8;
    const int b_lm_k   = ((lane >> 3) & 1) * 8;

    const uint32_t uA0 = smem_u32(As0), uA1 = smem_u32(As1);
    const uint32_t uB0 = smem_u32(Bs0), uB1 = smem_u32(Bs1);
    const uint32_t aoff = (uint32_t)(((wm * 32 + a_lm_row) * PITCH + a_lm_k) * 2);
    const uint32_t boff = (uint32_t)(((wn * 32 + b_lm_row) * PITCH + b_lm_k) * 2);

    // loaders
    const int a_row = tid >> 1, a_kh = (tid & 1) * 16;      // A: 16 floats/thread
    const int b_row = tid >> 2, b_k8 = (tid & 3) * 8;       // B: 1 cp16/array/thread
    const float* aG  = H + (size_t)(m0 + a_row) * DIM;
    const __half* b0G = g_W0 + (size_t)(blockIdx.y * CTA_N + b_row) * DIM;
    const __half* b1G = g_W1 + (size_t)(blockIdx.y * CTA_N + b_row) * DIM;
    const uint32_t b_sm_off = (uint32_t)((b_row * PITCH + b_k8) * 2);

    float acc_a[2][4][4], acc_c[2][4][4];
#pragma unroll
    for (int i = 0; i < 2; i++)
#pragma unroll
        for (int j = 0; j < 4; j++)
#pragma unroll
            for (int r = 0; r < 4; r++) { acc_a[i][j][r] = 0.f; acc_c[i][j][r] = 0.f; }
#pragma unroll
    for (int r = 0; r < 16; r++) acc2s[r * 256 + tid] = make_float2(0.f, 0.f);

    float4 av[4];
#pragma unroll
    for (int f = 0; f < 4; f++) av[f] = *(const float4*)(aG + a_kh + f * 4);

    auto store_a = [&](int stage) {
        __half* d0 = As0 + stage * ABUF + a_row * PITCH + a_kh;
        __half* d1 = As1 + stage * ABUF + a_row * PITCH + a_kh;
#pragma unroll
        for (int f = 0; f < 4; f++) {
            float fx = av[f].x, fy = av[f].y, fz = av[f].z, fw = av[f].w;
            __half2 p0 = __floats2half2_rn(fx, fy);
            __half2 p1 = __floats2half2_rn(fz, fw);
            float2 c0 = __half22float2(p0), c1 = __half22float2(p1);
            __half2 q0 = __floats2half2_rn((fx - c0.x) * 1024.f, (fy - c0.y) * 1024.f);
            __half2 q1 = __floats2half2_rn((fz - c1.x) * 1024.f, (fw - c1.y) * 1024.f);
            uint2 P, Q;
            P.x = *(uint32_t*)&p0; P.y = *(uint32_t*)&p1;
            Q.x = *(uint32_t*)&q0; Q.y = *(uint32_t*)&q1;
            *(uint2*)(d0 + f * 4) = P;     // 64-bit STS
            *(uint2*)(d1 + f * 4) = Q;
        }
    };
    auto issue_b = [&](int t, int stage) {
        cp16(uB0 + (uint32_t)(stage * BBUF * 2) + b_sm_off, b0G + t * KT + b_k8);
        cp16(uB1 + (uint32_t)(stage * BBUF * 2) + b_sm_off, b1G + t * KT + b_k8);
        CP_COMMIT();
    };

    store_a(0);
    issue_b(0, 0);
    CP_WAIT0();
    __syncthreads();

    for (int t = 0; t < NTILE; t++) {
        const int s = t & 1;
        const bool more = (t + 1 < NTILE);
        if (more) {
            issue_b(t + 1, s ^ 1);
            const int kb = (t + 1) * KT;
#pragma unroll
            for (int f = 0; f < 4; f++) av[f] = *(const float4*)(aG + kb + a_kh + f * 4);
        }

        const uint32_t stA0 = uA0 + (uint32_t)(s * ABUF * 2) + aoff;
        const uint32_t stA1 = uA1 + (uint32_t)(s * ABUF * 2) + aoff;
        const uint32_t stB0 = uB0 + (uint32_t)(s * BBUF * 2) + boff;
        const uint32_t stB1 = uB1 + (uint32_t)(s * BBUF * 2) + boff;

#pragma unroll
        for (int ks = 0; ks < 2; ks++) {
            const uint32_t kb2 = (uint32_t)(ks * 16 * 2);
            uint32_t a0f[2][4], b0f[4][2], b1f[4][2], a1f[2][4];
#pragma unroll
            for (int mt = 0; mt < 2; mt++)
                ldsm4(a0f[mt], stA0 + kb2 + (uint32_t)(mt * 16 * PITCH * 2));
            {
                uint32_t q[4];
                ldsm4(q, stB0 + kb2);
                b0f[0][0] = q[0]; b0f[0][1] = q[1]; b0f[1][0] = q[2]; b0f[1][1] = q[3];
                ldsm4(q, stB0 + kb2 + (uint32_t)(16 * PITCH * 2));
                b0f[2][0] = q[0]; b0f[2][1] = q[1]; b0f[3][0] = q[2]; b0f[3][1] = q[3];
            }
#pragma unroll
            for (int mt = 0; mt < 2; mt++)
#pragma unroll
                for (int nt = 0; nt < 4; nt++) mma16(acc_a[mt][nt], a0f[mt], b0f[nt]);
            {
                uint32_t q[4];
                ldsm4(q, stB1 + kb2);
                b1f[0][0] = q[0]; b1f[0][1] = q[1]; b1f[1][0] = q[2]; b1f[1][1] = q[3];
                ldsm4(q, stB1 + kb2 + (uint32_t)(16 * PITCH * 2));
                b1f[2][0] = q[0]; b1f[2][1] = q[1]; b1f[3][0] = q[2]; b1f[3][1] = q[3];
            }
#pragma unroll
            for (int mt = 0; mt < 2; mt++)
#pragma unroll
                for (int nt = 0; nt < 4; nt++) mma16(acc_c[mt][nt], a0f[mt], b1f[nt]);
#pragma unroll
            for (int mt = 0; mt < 2; mt++)
                ldsm4(a1f[mt], stA1 + kb2 + (uint32_t)(mt * 16 * PITCH * 2));
#pragma unroll
            for (int mt = 0; mt < 2; mt++)
#pragma unroll
                for (int nt = 0; nt < 4; nt++) mma16(acc_c[mt][nt], a1f[mt], b0f[nt]);
        }

        if (more) store_a(s ^ 1);
        CP_WAIT0();
        __syncthreads();

        if ((t & 3) == 3) {   // 128-k RN cascade (chunk doubled vs R15)
#pragma unroll
            for (int mt = 0; mt < 2; mt++)
#pragma unroll
                for (int nt = 0; nt < 4; nt++)
#pragma unroll
                    for (int rp = 0; rp < 2; rp++) {
                        float2* p = acc2s + ((mt * 4 + nt) * 2 + rp) * 256 + tid;
                        float2 v = *p;
                        v.x += acc_a[mt][nt][2*rp]   + acc_c[mt][nt][2*rp]   * CLO;
                        v.y += acc_a[mt][nt][2*rp+1] + acc_c[mt][nt][2*rp+1] * CLO;
                        *p = v;
                        acc_a[mt][nt][2*rp] = 0.f;   acc_c[mt][nt][2*rp] = 0.f;
                        acc_a[mt][nt][2*rp+1] = 0.f; acc_c[mt][nt][2*rp+1] = 0.f;
                    }
        }
    }

    // epilogue
#pragma unroll
    for (int mt = 0; mt < 2; mt++)
#pragma unroll
        for (int nt = 0; nt < 4; nt++) {
            const int row = m0 + wm * 32 + mt * 16 + fr;
            const int col = blockIdx.y * CTA_N + wn * 32 + nt * 8 + fc * 2;
            float2 v01 = acc2s[((mt * 4 + nt) * 2 + 0) * 256 + tid];
            float2 v23 = acc2s[((mt * 4 + nt) * 2 + 1) * 256 + tid];
            *(float2*)&g_logits[(size_t)row * NC + col]       = v01;
            *(float2*)&g_logits[(size_t)(row + 8) * NC + col] = v23;
        }
}

// ---------------------------------------------------------------------------
// Kernel 2: 2 tokens per warp (interleaved for SHFL ILP) — softmax + top-8
// ---------------------------------------------------------------------------
__device__ __forceinline__ float softplus_f(float x) {
    return fmaxf(x, 0.0f) + log1pf(expf(-fabsf(x)));
}

__global__ void __launch_bounds__(256)
router_topk_kernel(const float* __restrict__ noise, float* __restrict__ out) {
    const int wpair = (blockIdx.x * blockDim.x + threadIdx.x) >> 5;  // token pair
    const int lane  = threadIdx.x & 31;
    const int t0 = wpair * 2;
    if (t0 >= T_TOK) return;

    float g0[2], g1[2];
#pragma unroll
    for (int u = 0; u < 2; u++) {
        const float* row = g_logits + (size_t)(t0 + u) * NC;
        const float* nz  = noise + (size_t)(t0 + u) * N_EXP;
        g0[u] = row[lane]      + nz[lane]      * softplus_f(row[64 + lane]);
        g1[u] = row[lane + 32] + nz[lane + 32] * softplus_f(row[96 + lane]);
    }

    float mx[2] = { fmaxf(g0[0], g1[0]), fmaxf(g0[1], g1[1]) };
#pragma unroll
    for (int o = 16; o > 0; o >>= 1) {
        mx[0] = fmaxf(mx[0], __shfl_xor_sync(0xffffffffu, mx[0], o));
        mx[1] = fmaxf(mx[1], __shfl_xor_sync(0xffffffffu, mx[1], o));
    }
    float e0[2], e1[2], sum[2];
#pragma unroll
    for (int u = 0; u < 2; u++) {
        e0[u] = expf(g0[u] - mx[u]);
        e1[u] = expf(g1[u] - mx[u]);
        sum[u] = e0[u] + e1[u];
    }
#pragma unroll
    for (int o = 16; o > 0; o >>= 1) {
        sum[0] += __shfl_xor_sync(0xffffffffu, sum[0], o);
        sum[1] += __shfl_xor_sync(0xffffffffu, sum[1], o);
    }
    float p0[2], p1[2];
#pragma unroll
    for (int u = 0; u < 2; u++) {
        const float inv = 1.0f / sum[u];
        p0[u] = e0[u] * inv;
        p1[u] = e1[u] * inv;
        float* gates = out + (size_t)2 * T_TOK * TOPK + (size_t)(t0 + u) * N_EXP;
        gates[lane]      = p0[u];
        gates[lane + 32] = p1[u];
    }

    float v0[2] = { p0[0], p0[1] }, v1[2] = { p1[0], p1[1] };
#pragma unroll
    for (int r = 0; r < TOPK; r++) {
        float cv[2]; int ci[2];
#pragma unroll
        for (int u = 0; u < 2; u++) {
            if (v0[u] >= v1[u]) { cv[u] = v0[u]; ci[u] = lane; }
            else                { cv[u] = v1[u]; ci[u] = lane + 32; }
        }
#pragma unroll
        for (int o = 16; o > 0; o >>= 1) {
#pragma unroll
            for (int u = 0; u < 2; u++) {
                float ov = __shfl_xor_sync(0xffffffffu, cv[u], o);
                int   oi = __shfl_xor_sync(0xffffffffu, ci[u], o);
                if (ov > cv[u] || (ov == cv[u] && oi < ci[u])) { cv[u] = ov; ci[u] = oi; }
            }
        }
#pragma unroll
        for (int u = 0; u < 2; u++) {
            if (lane == 0) {
                out[(size_t)(t0 + u) * TOPK + r] = cv[u];
                out[(size_t)T_TOK * TOPK + (size_t)(t0 + u) * TOPK + r] = (float)ci[u];
            }
            if (ci[u] == lane)      v0[u] = -INFINITY;
            if (ci[u] == lane + 32) v1[u] = -INFINITY;
        }
    }
}

// ---------------------------------------------------------------------------
extern "C" void kernel_launch(void* const* d_in, const int* in_sizes, int n_in,
                              void* d_out, int out_size) {
    const float* H     = (const float*)d_in[0];
    const float* Wg    = (const float*)d_in[1];
    const float* Wn    = (const float*)d_in[2];
    const float* noise = (const float*)d_in[3];
    float* out = (float*)d_out;

    cudaFuncSetAttribute(router_gemm_f16,
                         cudaFuncAttributeMaxDynamicSharedMemorySize, DYN_SMEM);

    wsplit_kernel<<<256, 256>>>(Wg, Wn);
    dim3 grid(T_TOK / CTA_M, 2);
    router_gemm_f16<<<grid, 256, DYN_SMEM>>>(H);
    router_topk_kernel<<<(T_TOK / 2 * 32) / 256, 256>>>(noise, out);
}